// round 2
// baseline (speedup 1.0000x reference)
#include <cuda_runtime.h>
#include <cstdint>

// Problem constants (fixed by the reference):
//   B = 8192 rows
//   slice_input: [B, 16384] f32
//   unmatched:   [B, 256]   f32
//   where:       [B, 1]     bool (dtype after harness serialization UNKNOWN:
//                                 could be uint8, int32, or float32 — detect!)
//   output:      [B, 256 + 64*128] = [B, 8448] f32
// gathered[s*128 + j] = slice[s*256 + j]   (static strided gather)

static constexpr int B_ROWS      = 8192;
static constexpr int D_SLICE     = 16384;
static constexpr int D_UNM       = 256;
static constexpr int D_GATHER    = 64 * 128;          // 8192
static constexpr int D_OUT       = D_UNM + D_GATHER;  // 8448

// In float4 units:
static constexpr int V_SLICE_ROW = D_SLICE / 4;   // 4096
static constexpr int V_UNM_ROW   = D_UNM / 4;     // 64
static constexpr int V_OUT_ROW   = D_OUT / 4;     // 2112
static constexpr int V_STRIDE    = 256 / 4;       // 64 float4 source stride per slice

// Scratch: decoded per-row mask (allocation-free rule: __device__ global).
__device__ uint8_t g_mask[B_ROWS];

// ---------------------------------------------------------------------------
// Prepass: detect where-dtype from byte pattern, decode mask.
// One block, 1024 threads. Reads at most 8192 bytes in detection phase
// (safe for 1-byte AND 4-byte encodings); reads words only if 4-byte.
// ---------------------------------------------------------------------------
__global__ void decode_mask_kernel(const uint8_t* __restrict__ raw)
{
    __shared__ int s_off1_nz;   // nonzero byte seen at offset % 4 == 1
    __shared__ int s_off23_nz;  // nonzero byte seen at offset % 4 in {2,3}

    if (threadIdx.x == 0) { s_off1_nz = 0; s_off23_nz = 0; }
    __syncthreads();

    int off1 = 0, off23 = 0;
    for (int i = threadIdx.x; i < B_ROWS; i += blockDim.x) {
        uint8_t b = raw[i];
        int m = i & 3;
        if (b != 0) {
            if (m == 1) off1 = 1;
            if (m == 2 || m == 3) off23 = 1;
        }
    }
    if (off1)  atomicOr(&s_off1_nz, 1);
    if (off23) atomicOr(&s_off23_nz, 1);
    __syncthreads();

    const bool is_u8   = (s_off1_nz != 0);
    // if not u8: 4-byte words; value nonzero <=> word nonzero (covers int32
    // 0/1 and float32 0.0/1.0 alike). s_off23_nz only tells us it's float,
    // but we don't need to distinguish — word test works for both.
    (void)s_off23_nz;

    if (is_u8) {
        for (int i = threadIdx.x; i < B_ROWS; i += blockDim.x)
            g_mask[i] = (raw[i] != 0) ? 1 : 0;
    } else {
        const uint32_t* w = (const uint32_t*)raw;
        for (int i = threadIdx.x; i < B_ROWS; i += blockDim.x)
            g_mask[i] = (w[i] != 0) ? 1 : 0;
    }
}

// ---------------------------------------------------------------------------
// Main streaming kernel: one CTA per row.
// ---------------------------------------------------------------------------
__global__ __launch_bounds__(256)
void fused_slice_where_cat_kernel(const float4* __restrict__ slice_in,
                                  const float4* __restrict__ unmatched,
                                  float4*       __restrict__ out)
{
    const int row = blockIdx.x;
    const bool w = g_mask[row] != 0;

    const float4* __restrict__ srow = slice_in  + (size_t)row * V_SLICE_ROW;
    const float4* __restrict__ urow = unmatched + (size_t)row * V_UNM_ROW;
    float4*       __restrict__ orow = out       + (size_t)row * V_OUT_ROW;

    const float4 zero = make_float4(0.f, 0.f, 0.f, 0.f);

    #pragma unroll 4
    for (int v = threadIdx.x; v < V_OUT_ROW; v += 256) {
        float4 val;
        if (v < V_UNM_ROW) {
            val = urow[v];
        } else if (w) {
            const int g = v - V_UNM_ROW;     // 0..2047
            const int s = g >> 5;            // slice chunk (g / 32)
            const int j = g & 31;            // float4 within 128-f32 chunk
            val = srow[s * V_STRIDE + j];
        } else {
            val = zero;
        }
        orow[v] = val;
    }
}

extern "C" void kernel_launch(void* const* d_in, const int* in_sizes, int n_in,
                              void* d_out, int out_size)
{
    // Identify inputs by element count (robust against scalar cat_dim /
    // slice_dim inputs and against input-order changes).
    const uint8_t* where_raw = nullptr;
    const float*   slice_in  = nullptr;
    const float*   unmatched = nullptr;

    for (int i = 0; i < n_in; i++) {
        const long long n = in_sizes[i];
        if (n == (long long)B_ROWS) {
            where_raw = (const uint8_t*)d_in[i];
        } else if (n == (long long)B_ROWS * D_SLICE) {
            slice_in = (const float*)d_in[i];
        } else if (n == (long long)B_ROWS * D_UNM) {
            unmatched = (const float*)d_in[i];
        }
    }

    decode_mask_kernel<<<1, 1024>>>(where_raw);
    fused_slice_where_cat_kernel<<<B_ROWS, 256>>>(
        (const float4*)slice_in,
        (const float4*)unmatched,
        (float4*)d_out);
}

// round 3
// speedup vs baseline: 1.0841x; 1.0841x over previous
#include <cuda_runtime.h>
#include <cstdint>

// Problem constants (fixed by the reference):
//   B = 8192 rows
//   slice_input: [B, 16384] f32
//   unmatched:   [B, 256]   f32
//   where:       [B, 1]     4-byte type (int32 or float32; established
//                           empirically R1/R2 — word != 0 decodes both)
//   output:      [B, 8448]  f32   (256 unmatched ++ 8192 gathered)
// gathered[s*128 + j] = slice[s*256 + j]   (static strided gather)

static constexpr int B_ROWS      = 8192;
static constexpr int D_SLICE     = 16384;
static constexpr int D_UNM       = 256;

// float4 units:
static constexpr int V_SLICE_ROW = D_SLICE / 4;        // 4096
static constexpr int V_UNM_ROW   = D_UNM / 4;          // 64
static constexpr int V_GATHER    = 2048;               // 8192 f32 / 4
static constexpr int V_OUT_ROW   = V_UNM_ROW + V_GATHER; // 2112
static constexpr int V_STRIDE    = 64;                 // 256 f32 / 4 per slice chunk

// One CTA per row, 256 threads. Gather region: exactly 8 float4 per thread.
// Front-batch all loads (MLP ~9), then all stores. Streaming cache hints.
__global__ __launch_bounds__(256)
void fused_slice_where_cat_kernel(const uint32_t* __restrict__ mask_words,
                                  const float4*   __restrict__ slice_in,
                                  const float4*   __restrict__ unmatched,
                                  float4*         __restrict__ out)
{
    const int row = blockIdx.x;
    const int t   = threadIdx.x;
    const bool w  = mask_words[row] != 0u;

    const float4* __restrict__ srow = slice_in  + (size_t)row * V_SLICE_ROW;
    const float4* __restrict__ urow = unmatched + (size_t)row * V_UNM_ROW;
    float4*       __restrict__ orow = out       + (size_t)row * V_OUT_ROW;

    const float4 zero = make_float4(0.f, 0.f, 0.f, 0.f);

    // ---- batched loads (independent, in flight together) ----
    float4 uval = zero;
    if (t < V_UNM_ROW) uval = __ldcs(&urow[t]);

    float4 vals[8];
    if (w) {
        #pragma unroll
        for (int k = 0; k < 8; k++) {
            const int g = t + k * 256;         // 0..2047
            const int s = g >> 5;              // slice chunk
            const int j = g & 31;              // float4 within 128-f32 chunk
            vals[k] = __ldcs(&srow[s * V_STRIDE + j]);
        }
    } else {
        #pragma unroll
        for (int k = 0; k < 8; k++) vals[k] = zero;
    }

    // ---- batched stores ----
    if (t < V_UNM_ROW) __stcs(&orow[t], uval);

    float4* __restrict__ grow = orow + V_UNM_ROW;
    #pragma unroll
    for (int k = 0; k < 8; k++)
        __stcs(&grow[t + k * 256], vals[k]);
}

extern "C" void kernel_launch(void* const* d_in, const int* in_sizes, int n_in,
                              void* d_out, int out_size)
{
    // Identify inputs by element count (robust against scalar cat_dim /
    // slice_dim inputs and against input-order changes).
    const uint32_t* where_raw = nullptr;
    const float*    slice_in  = nullptr;
    const float*    unmatched = nullptr;

    for (int i = 0; i < n_in; i++) {
        const long long n = in_sizes[i];
        if (n == (long long)B_ROWS) {
            where_raw = (const uint32_t*)d_in[i];
        } else if (n == (long long)B_ROWS * D_SLICE) {
            slice_in = (const float*)d_in[i];
        } else if (n == (long long)B_ROWS * D_UNM) {
            unmatched = (const float*)d_in[i];
        }
    }

    fused_slice_where_cat_kernel<<<B_ROWS, 256>>>(
        where_raw,
        (const float4*)slice_in,
        (const float4*)unmatched,
        (float4*)d_out);
}

// round 4
// speedup vs baseline: 1.0883x; 1.0039x over previous
#include <cuda_runtime.h>
#include <cstdint>

// Problem constants (fixed by the reference):
//   B = 8192 rows
//   slice_input: [B, 16384] f32
//   unmatched:   [B, 256]   f32
//   where:       [B, 1]     4-byte word (int32/float32; word!=0 decodes both,
//                           established empirically R1/R2)
//   output:      [B, 8448]  f32   (256 unmatched ++ 8192 gathered)
// gathered[s*128 + j] = slice[s*256 + j]   (static strided gather)

static constexpr int B_ROWS      = 8192;
static constexpr int D_SLICE     = 16384;
static constexpr int D_UNM       = 256;

// float4 units:
static constexpr int V_SLICE_ROW = D_SLICE / 4;          // 4096
static constexpr int V_UNM_ROW   = D_UNM / 4;            // 64
static constexpr int V_GATHER    = 2048;                 // 8192 f32 / 4
static constexpr int V_OUT_ROW   = V_UNM_ROW + V_GATHER; // 2112
static constexpr int V_STRIDE    = 64;                   // 256 f32 / 4 per chunk

// One CTA per row, 512 threads, 4 gather float4 per thread (16 payload regs).
// __launch_bounds__(512, 4) caps regs at 32 -> 2048 threads/SM resident.
// Loads front-batched (independent), stores after. Streaming cache hints.
__global__ __launch_bounds__(512, 4)
void fused_slice_where_cat_kernel(const uint32_t* __restrict__ mask_words,
                                  const float4*   __restrict__ slice_in,
                                  const float4*   __restrict__ unmatched,
                                  float4*         __restrict__ out)
{
    const int row = blockIdx.x;
    const int t   = threadIdx.x;
    const bool w  = mask_words[row] != 0u;

    const float4* __restrict__ srow = slice_in  + (size_t)row * V_SLICE_ROW;
    const float4* __restrict__ urow = unmatched + (size_t)row * V_UNM_ROW;
    float4*       __restrict__ orow = out       + (size_t)row * V_OUT_ROW;

    const float4 zero = make_float4(0.f, 0.f, 0.f, 0.f);

    // ---- batched independent loads ----
    float4 uval = zero;
    if (t < V_UNM_ROW) uval = __ldcs(&urow[t]);

    float4 vals[4];
    if (w) {
        #pragma unroll
        for (int k = 0; k < 4; k++) {
            const int g = t + k * 512;          // 0..2047
            const int s = g >> 5;               // slice chunk (g / 32)
            const int j = g & 31;               // float4 within 128-f32 chunk
            vals[k] = __ldcs(&srow[s * V_STRIDE + j]);
        }
    } else {
        #pragma unroll
        for (int k = 0; k < 4; k++) vals[k] = zero;
    }

    // ---- batched stores ----
    if (t < V_UNM_ROW) __stcs(&orow[t], uval);

    float4* __restrict__ grow = orow + V_UNM_ROW;
    #pragma unroll
    for (int k = 0; k < 4; k++)
        __stcs(&grow[t + k * 512], vals[k]);
}

extern "C" void kernel_launch(void* const* d_in, const int* in_sizes, int n_in,
                              void* d_out, int out_size)
{
    // Identify inputs by element count (robust against scalar cat_dim /
    // slice_dim inputs and against input-order changes).
    const uint32_t* where_raw = nullptr;
    const float*    slice_in  = nullptr;
    const float*    unmatched = nullptr;

    for (int i = 0; i < n_in; i++) {
        const long long n = in_sizes[i];
        if (n == (long long)B_ROWS) {
            where_raw = (const uint32_t*)d_in[i];
        } else if (n == (long long)B_ROWS * D_SLICE) {
            slice_in = (const float*)d_in[i];
        } else if (n == (long long)B_ROWS * D_UNM) {
            unmatched = (const float*)d_in[i];
        }
    }

    fused_slice_where_cat_kernel<<<B_ROWS, 512>>>(
        where_raw,
        (const float4*)slice_in,
        (const float4*)unmatched,
        (float4*)d_out);
}

// round 5
// speedup vs baseline: 1.0925x; 1.0039x over previous
#include <cuda_runtime.h>
#include <cstdint>

// Problem constants (fixed by the reference):
//   B = 8192 rows
//   slice_input: [B, 16384] f32
//   unmatched:   [B, 256]   f32
//   where:       [B, 1]     4-byte word (int32/float32; word!=0 decodes both,
//                           established empirically R1/R2)
//   output:      [B, 8448]  f32   (256 unmatched ++ 8192 gathered)
// gathered[s*128 + j] = slice[s*256 + j]   (static strided gather)

static constexpr int B_ROWS   = 8192;
static constexpr int D_SLICE  = 16384;
static constexpr int D_UNM    = 256;
static constexpr int D_OUT    = 8448;

// ---- 256-bit (v8.f32) global memory ops — Blackwell sm_100+ ----
__device__ __forceinline__ void ldg_v8_cs(float* r, const float* p) {
    asm volatile("ld.global.cs.v8.f32 {%0,%1,%2,%3,%4,%5,%6,%7}, [%8];"
                 : "=f"(r[0]), "=f"(r[1]), "=f"(r[2]), "=f"(r[3]),
                   "=f"(r[4]), "=f"(r[5]), "=f"(r[6]), "=f"(r[7])
                 : "l"(p));
}
__device__ __forceinline__ void stg_v8_cs(float* p, const float* r) {
    asm volatile("st.global.cs.v8.f32 [%0], {%1,%2,%3,%4,%5,%6,%7,%8};"
                 :: "l"(p),
                    "f"(r[0]), "f"(r[1]), "f"(r[2]), "f"(r[3]),
                    "f"(r[4]), "f"(r[5]), "f"(r[6]), "f"(r[7])
                 : "memory");
}

// One CTA per row, 512 threads.
// Gather region = 8192 f32 = 1024 v8-units; each thread handles units
// {t, t+512}. Unmatched region = 32 v8-units, threads 0..31 (register block
// reused before the gather loads, so payload stays at 16 regs).
// v8-unit u (8 f32): chunk s = u>>4, within-chunk f32 offset = (u&15)*8,
// source f32 offset = s*256 + (u&15)*8.
__global__ __launch_bounds__(512, 4)
void fused_slice_where_cat_kernel(const uint32_t* __restrict__ mask_words,
                                  const float*    __restrict__ slice_in,
                                  const float*    __restrict__ unmatched,
                                  float*          __restrict__ out)
{
    const int row = blockIdx.x;
    const int t   = threadIdx.x;
    const bool w  = mask_words[row] != 0u;

    const float* __restrict__ srow = slice_in  + (size_t)row * D_SLICE;
    const float* __restrict__ urow = unmatched + (size_t)row * D_UNM;
    float*       __restrict__ orow = out       + (size_t)row * D_OUT;

    float r0[8], r1[8];

    // ---- unmatched copy (threads 0..31, one v8 unit each) ----
    if (t < 32) {
        ldg_v8_cs(r0, urow + t * 8);
        stg_v8_cs(orow + t * 8, r0);
    }

    // ---- gather: two v8 units per thread, loads batched ----
    const int u0 = t;            // 0..511
    const int u1 = t + 512;      // 512..1023

    if (w) {
        const int src0 = ((u0 >> 4) << 8) + ((u0 & 15) << 3);  // s*256 + (u&15)*8
        const int src1 = ((u1 >> 4) << 8) + ((u1 & 15) << 3);
        ldg_v8_cs(r0, srow + src0);
        ldg_v8_cs(r1, srow + src1);
    } else {
        #pragma unroll
        for (int i = 0; i < 8; i++) { r0[i] = 0.f; r1[i] = 0.f; }
    }

    float* __restrict__ grow = orow + D_UNM;
    stg_v8_cs(grow + u0 * 8, r0);
    stg_v8_cs(grow + u1 * 8, r1);
}

extern "C" void kernel_launch(void* const* d_in, const int* in_sizes, int n_in,
                              void* d_out, int out_size)
{
    // Identify inputs by element count (robust against scalar cat_dim /
    // slice_dim inputs and against input-order changes).
    const uint32_t* where_raw = nullptr;
    const float*    slice_in  = nullptr;
    const float*    unmatched = nullptr;

    for (int i = 0; i < n_in; i++) {
        const long long n = in_sizes[i];
        if (n == (long long)B_ROWS) {
            where_raw = (const uint32_t*)d_in[i];
        } else if (n == (long long)B_ROWS * D_SLICE) {
            slice_in = (const float*)d_in[i];
        } else if (n == (long long)B_ROWS * D_UNM) {
            unmatched = (const float*)d_in[i];
        }
    }

    fused_slice_where_cat_kernel<<<B_ROWS, 512>>>(
        where_raw, slice_in, unmatched, (float*)d_out);
}